// round 2
// baseline (speedup 1.0000x reference)
#include <cuda_runtime.h>
#include <cstdint>

// Problem constants (x = [4096, 8192, 1] f32, G = 7)
constexpr int B_ROWS = 4096;
constexpr int I_COLS = 8192;
constexpr int G      = 7;

constexpr int BT    = 1024;          // threads per block
constexpr int IPT   = 8;             // items per thread
constexpr int NWARP = BT / 32;       // 32 warps
constexpr int NDIG  = 256;           // 8-bit digits
constexpr int NPASS = 4;             // 4 x 8 bits = 32

// Dynamic shared memory layout:
//   hist : NWARP*NDIG u32  = 32 KB   (per-warp digit histograms / offsets)
//   buf  : I_COLS u64      = 64 KB   (fused key|index scatter buffer)
//   aux  : 64 u32                    (block-scan warp totals)
//   scal : 16 f32                    (winner/loser softmax results)
constexpr int HIST_WORDS = NWARP * NDIG;                 // 8192
constexpr size_t OFF_BUF  = HIST_WORDS * 4;              // 32768
constexpr size_t OFF_AUX  = OFF_BUF + (size_t)I_COLS * 8; // +65536
constexpr size_t OFF_SCAL = OFF_AUX + 64 * 4;
constexpr size_t SMEM_BYTES = OFF_SCAL + 16 * 4;

__device__ __forceinline__ uint32_t fwd_key(uint32_t b) {
    // ascending sort of this key == descending sort of the float
    uint32_t m = (uint32_t)(((int32_t)b) >> 31) | 0x80000000u;
    return ~(b ^ m);
}
__device__ __forceinline__ float inv_key(uint32_t k) {
    uint32_t u = ~k;                      // ascending-mapped bits
    uint32_t b = (u & 0x80000000u) ? (u ^ 0x80000000u) : ~u;
    return __uint_as_float(b);
}

extern __shared__ unsigned char smem_raw[];

__global__ void __launch_bounds__(BT, 1)
portfolio_radix8_kernel(const float* __restrict__ x, float* __restrict__ out)
{
    uint32_t*           hist = (uint32_t*)smem_raw;
    unsigned long long* buf  = (unsigned long long*)(smem_raw + OFF_BUF);
    uint32_t*           aux  = (uint32_t*)(smem_raw + OFF_AUX);
    float*              scal = (float*)(smem_raw + OFF_SCAL);

    const int tid  = threadIdx.x;
    const int wid  = tid >> 5;
    const int lane = tid & 31;
    const int row  = blockIdx.x;

    const float* xr = x + (size_t)row * I_COLS;

    // Arrangement: item slot s of thread (w,lane) sits at position
    //   p = w*256 + s*32 + lane
    // Position order == (warp major, slot, lane) which is exactly the order
    // the ranking below counts in -> fully stable sort (ties -> index asc),
    // matching jnp.argsort(-x).
    uint32_t key[IPT], val[IPT], rnk[IPT];
    #pragma unroll
    for (int s = 0; s < IPT; s++) {
        int p = (wid << 8) + (s << 5) + lane;
        key[s] = fwd_key(__float_as_uint(xr[p]));
        val[s] = (uint32_t)p;
    }

    #pragma unroll
    for (int pass = 0; pass < NPASS; pass++) {
        const int shift = pass * 8;

        // ---- zero per-warp histograms ----
        #pragma unroll
        for (int i = 0; i < HIST_WORDS / BT; i++) hist[tid * (HIST_WORDS / BT) + i] = 0;
        __syncthreads();

        // ---- Phase A: warp-level multi-split ranking (slot-major order) ----
        #pragma unroll
        for (int s = 0; s < IPT; s++) {
            uint32_t d    = (key[s] >> shift) & (NDIG - 1);
            unsigned mask = __match_any_sync(0xFFFFFFFFu, d);
            unsigned ltm  = mask & ((1u << lane) - 1u);
            int   leader  = __ffs(mask) - 1;
            uint32_t base = 0;
            if (lane == leader) {
                base = hist[wid * NDIG + d];
                hist[wid * NDIG + d] = base + (uint32_t)__popc(mask);
            }
            base   = __shfl_sync(0xFFFFFFFFu, base, leader);
            rnk[s] = base + (uint32_t)__popc(ltm);
        }
        __syncthreads();

        // ---- Phase B: in-place exclusive scan over logical order j = d*32 + w
        //      (physical address for j is w*256 + d) ----
        {
            uint32_t e[8], sum = 0;
            #pragma unroll
            for (int i = 0; i < 8; i++) {
                int j = tid * 8 + i;
                uint32_t v = hist[((j & 31) << 8) + (j >> 5)];
                e[i] = sum; sum += v;
            }
            uint32_t inc = sum;
            #pragma unroll
            for (int o = 1; o < 32; o <<= 1) {
                uint32_t n = __shfl_up_sync(0xFFFFFFFFu, inc, o);
                if (lane >= o) inc += n;
            }
            if (lane == 31) aux[wid] = inc;
            __syncthreads();
            if (wid == 0) {
                uint32_t t  = aux[lane];
                uint32_t ti = t;
                #pragma unroll
                for (int o = 1; o < 32; o <<= 1) {
                    uint32_t n = __shfl_up_sync(0xFFFFFFFFu, ti, o);
                    if (lane >= o) ti += n;
                }
                aux[lane] = ti - t;   // exclusive warp prefix
            }
            __syncthreads();
            uint32_t base = aux[wid] + (inc - sum);
            #pragma unroll
            for (int i = 0; i < 8; i++) {
                int j = tid * 8 + i;
                hist[((j & 31) << 8) + (j >> 5)] = base + e[i];
            }
        }
        __syncthreads();

        // ---- Phase C: fused (key|index) 64-bit scatter ----
        #pragma unroll
        for (int s = 0; s < IPT; s++) {
            uint32_t d   = (key[s] >> shift) & (NDIG - 1);
            uint32_t pos = hist[wid * NDIG + d] + rnk[s];
            buf[pos] = ((unsigned long long)key[s] << 32) | (unsigned long long)val[s];
        }
        __syncthreads();

        // ---- gather back (skip after final pass; epilogue reads buf) ----
        if (pass < NPASS - 1) {
            #pragma unroll
            for (int s = 0; s < IPT; s++) {
                unsigned long long kv = buf[(wid << 8) + (s << 5) + lane];
                key[s] = (uint32_t)(kv >> 32);
                val[s] = (uint32_t)(kv & 0xFFFFFFFFu);
            }
            // no sync needed here: next write to buf is 3 barriers away
        }
    }

    // ---- epilogue: softmaxes over top-G / bottom-G sorted values ----
    if (tid == 0) {
        float t[G], b[G];
        #pragma unroll
        for (int i = 0; i < G; i++) t[i] = inv_key((uint32_t)(buf[i] >> 32));
        #pragma unroll
        for (int i = 0; i < G; i++) b[i] = inv_key((uint32_t)(buf[I_COLS - G + i] >> 32));

        float m = t[0];
        #pragma unroll
        for (int i = 1; i < G; i++) m = fmaxf(m, t[i]);
        float e[G], s = 0.0f;
        #pragma unroll
        for (int i = 0; i < G; i++) { e[i] = expf(t[i] - m); s += e[i]; }
        float invs = 1.0f / s;
        #pragma unroll
        for (int i = 0; i < G; i++) scal[i] = e[i] * invs;

        float m2 = 1.0f - b[0];
        #pragma unroll
        for (int i = 1; i < G; i++) m2 = fmaxf(m2, 1.0f - b[i]);
        float e2[G], s2 = 0.0f;
        #pragma unroll
        for (int i = 0; i < G; i++) { e2[i] = expf((1.0f - b[i]) - m2); s2 += e2[i]; }
        float invs2 = 1.0f / s2;
        #pragma unroll
        for (int i = 0; i < G; i++) scal[G + i] = -e2[i] * invs2;
    }
    __syncthreads();

    // ---- write b_c and sorted_indices (both as f32), fully coalesced ----
    float* bc = out + (size_t)row * I_COLS;
    float* si = out + (size_t)B_ROWS * I_COLS + (size_t)row * I_COLS;
    #pragma unroll
    for (int s = 0; s < IPT; s++) {
        int r = (wid << 8) + (s << 5) + lane;
        unsigned long long kv = buf[r];
        float v = 0.0f;
        if (r < G)                v = scal[r];
        else if (r >= I_COLS - G) v = scal[G + r - (I_COLS - G)];
        bc[r] = v;
        si[r] = (float)(uint32_t)(kv & 0xFFFFFFFFu);
    }
}

extern "C" void kernel_launch(void* const* d_in, const int* in_sizes, int n_in,
                              void* d_out, int out_size)
{
    (void)in_sizes; (void)n_in; (void)out_size;
    const float* x = (const float*)d_in[0];
    float* out = (float*)d_out;

    cudaFuncSetAttribute(portfolio_radix8_kernel,
                         cudaFuncAttributeMaxDynamicSharedMemorySize,
                         (int)SMEM_BYTES);
    portfolio_radix8_kernel<<<B_ROWS, BT, SMEM_BYTES>>>(x, out);
}